// round 1
// baseline (speedup 1.0000x reference)
#include <cuda_runtime.h>

#define EPS 1e-8f
#define NBLOCKS 2048
#define NTHREADS 256

__device__ float g_partials[NBLOCKS];

__global__ __launch_bounds__(NTHREADS) void cce_partial_kernel(
    const float* __restrict__ input,
    const float* __restrict__ target,
    long long n4)   // number of float4 elements
{
    const float4* __restrict__ in4 = (const float4*)input;
    const float4* __restrict__ tg4 = (const float4*)target;

    float acc = 0.0f;
    long long idx = (long long)blockIdx.x * NTHREADS + threadIdx.x;
    long long stride = (long long)NBLOCKS * NTHREADS;

    for (; idx < n4; idx += stride) {
        float4 a = in4[idx];
        float4 t = tg4[idx];
        acc += a.x * __logf(t.x + EPS);
        acc += a.y * __logf(t.y + EPS);
        acc += a.z * __logf(t.z + EPS);
        acc += a.w * __logf(t.w + EPS);
    }

    // warp reduce
    #pragma unroll
    for (int off = 16; off > 0; off >>= 1)
        acc += __shfl_xor_sync(0xFFFFFFFFu, acc, off);

    __shared__ float warp_sums[NTHREADS / 32];
    int lane = threadIdx.x & 31;
    int wid  = threadIdx.x >> 5;
    if (lane == 0) warp_sums[wid] = acc;
    __syncthreads();

    if (wid == 0) {
        float v = (lane < NTHREADS / 32) ? warp_sums[lane] : 0.0f;
        #pragma unroll
        for (int off = 16; off > 0; off >>= 1)
            v += __shfl_xor_sync(0xFFFFFFFFu, v, off);
        if (lane == 0) g_partials[blockIdx.x] = v;
    }
}

__global__ __launch_bounds__(1024) void cce_final_kernel(float* __restrict__ out, float inv_b)
{
    // 1024 threads, each sums NBLOCKS/1024 = 2 partials in double
    double acc = 0.0;
    for (int i = threadIdx.x; i < NBLOCKS; i += 1024)
        acc += (double)g_partials[i];

    // warp reduce in double
    #pragma unroll
    for (int off = 16; off > 0; off >>= 1)
        acc += __shfl_xor_sync(0xFFFFFFFFu, acc, off);

    __shared__ double warp_sums[32];
    int lane = threadIdx.x & 31;
    int wid  = threadIdx.x >> 5;
    if (lane == 0) warp_sums[wid] = acc;
    __syncthreads();

    if (wid == 0) {
        double v = (lane < 32) ? warp_sums[lane] : 0.0;
        #pragma unroll
        for (int off = 16; off > 0; off >>= 1)
            v += __shfl_xor_sync(0xFFFFFFFFu, v, off);
        if (lane == 0)
            out[0] = (float)(-v * (double)inv_b);
    }
}

extern "C" void kernel_launch(void* const* d_in, const int* in_sizes, int n_in,
                              void* d_out, int out_size)
{
    const float* input  = (const float*)d_in[0];
    const float* target = (const float*)d_in[1];
    float* out = (float*)d_out;

    long long n = (long long)in_sizes[0];     // 262144 * 128 = 33554432, divisible by 4
    long long n4 = n >> 2;
    long long B = 262144;                      // rows; n / 128
    // derive B robustly: C = 128 known from problem; but compute from sizes anyway
    // n = B * C with C = 128
    B = n / 128;

    cce_partial_kernel<<<NBLOCKS, NTHREADS>>>(input, target, n4);
    cce_final_kernel<<<1, 1024>>>(out, 1.0f / (float)B);
}